// round 1
// baseline (speedup 1.0000x reference)
#include <cuda_runtime.h>
#include <math.h>
#include <stdint.h>

#define B_  2
#define S_  2048
#define H_  16
#define D_  64
#define DM_ 1024
#define BH_ (B_ * H_)

// -------- scratch (device globals: allocation-free) --------
__device__ float g_q[(size_t)BH_ * S_ * D_];
__device__ float g_k[(size_t)BH_ * S_ * D_];
__device__ float g_v[(size_t)BH_ * S_ * D_];
__device__ float g_o2[(size_t)BH_ * S_ * D_];
__device__ float g_ctx[(size_t)BH_ * S_ * D_];
__device__ float g_normed[(size_t)B_ * S_ * DM_];

// ============================================================
// Kernel 1: QKV projection.  C[m,n] = sum_k x[m,k]*W[n,k] + b[n]
// M = B*S = 4096, N = 3*DM = 3072, K = 1024.
// Epilogue scatters into g_q/g_k/g_v in (b,h,s,d) layout.
// ============================================================
__global__ void __launch_bounds__(256) qkv_gemm_kernel(
    const float* __restrict__ x, const float* __restrict__ W,
    const float* __restrict__ bias) {
    __shared__ float As[16][68];
    __shared__ float Bs[16][68];
    const int bm = blockIdx.y * 64;
    const int bn = blockIdx.x * 64;
    const int tid = threadIdx.x;
    const int tx = tid & 15, ty = tid >> 4;
    const int lr = tid >> 2;             // 0..63 tile row
    const int lc = (tid & 3) * 4;        // 0,4,8,12 within BK=16

    float acc[4][4] = {};
    for (int k0 = 0; k0 < 1024; k0 += 16) {
        float4 a = *(const float4*)&x[(size_t)(bm + lr) * 1024 + k0 + lc];
        float4 b = *(const float4*)&W[(size_t)(bn + lr) * 1024 + k0 + lc];
        As[lc + 0][lr] = a.x; As[lc + 1][lr] = a.y;
        As[lc + 2][lr] = a.z; As[lc + 3][lr] = a.w;
        Bs[lc + 0][lr] = b.x; Bs[lc + 1][lr] = b.y;
        Bs[lc + 2][lr] = b.z; Bs[lc + 3][lr] = b.w;
        __syncthreads();
#pragma unroll
        for (int kk = 0; kk < 16; kk++) {
            float av[4], bv[4];
#pragma unroll
            for (int i = 0; i < 4; i++) av[i] = As[kk][ty * 4 + i];
#pragma unroll
            for (int j = 0; j < 4; j++) bv[j] = Bs[kk][tx * 4 + j];
#pragma unroll
            for (int i = 0; i < 4; i++)
#pragma unroll
                for (int j = 0; j < 4; j++) acc[i][j] += av[i] * bv[j];
        }
        __syncthreads();
    }
    // scatter epilogue
#pragma unroll
    for (int i = 0; i < 4; i++) {
        const int m = bm + ty * 4 + i;
        const int b_idx = m / S_, s_idx = m % S_;
#pragma unroll
        for (int j = 0; j < 4; j++) {
            const int n = bn + tx * 4 + j;
            const float val = acc[i][j] + bias[n];
            const int which = n >> 10;       // /DM
            const int wi = n & 1023;
            const int h = wi >> 6, d = wi & 63;
            float* dst = (which == 0) ? g_q : (which == 1) ? g_k : g_v;
            dst[(((size_t)b_idx * H_ + h) * S_ + s_idx) * D_ + d] = val;
        }
    }
}

// ============================================================
// Kernel 2/3: causal no-softmax attention pass (flash-style).
// MODE 0: Qeff = q,        V = k,  Out = o2
// MODE 1: Qeff = 2q - o2,  V = v,  Out = ctx
// Block: 64 queries x D=64, loops over key blocks j <= qi.
// ============================================================
template <int MODE>
__global__ void __launch_bounds__(256) attn_kernel() {
    extern __shared__ float sm[];
    float* Qs = sm;                       // 64 x 65
    float* Ks = sm + 64 * 65;
    float* Ss = sm + 2 * 64 * 65;
    float* Vs = (MODE == 0) ? Ks : sm + 3 * 64 * 65;

    const int bh = blockIdx.y;
    const int qi = blockIdx.x;
    const size_t base = (size_t)bh * S_ * D_;
    const int t0 = qi * 64;
    const int tid = threadIdx.x;
    const int tx = tid & 15, ty = tid >> 4;
    const int lr = tid >> 2;              // row loader 0..63
    const int lc0 = (tid & 3) * 16;       // 16 floats per thread

    // load Q block (Qeff)
    {
        const float* qp = g_q + base + (size_t)(t0 + lr) * D_;
        const float* op = g_o2 + base + (size_t)(t0 + lr) * D_;
#pragma unroll
        for (int u = 0; u < 4; u++) {
            const int c = lc0 + u * 4;
            float4 a = *(const float4*)(qp + c);
            if (MODE == 1) {
                float4 o = *(const float4*)(op + c);
                a.x = 2.f * a.x - o.x; a.y = 2.f * a.y - o.y;
                a.z = 2.f * a.z - o.z; a.w = 2.f * a.w - o.w;
            }
            Qs[lr * 65 + c + 0] = a.x; Qs[lr * 65 + c + 1] = a.y;
            Qs[lr * 65 + c + 2] = a.z; Qs[lr * 65 + c + 3] = a.w;
        }
    }

    float acc[4][4] = {};
    for (int j = 0; j <= qi; j++) {
        const int s0 = j * 64;
        __syncthreads();   // prev iter done with Ks/Vs/Ss
        {
            const float* kp = g_k + base + (size_t)(s0 + lr) * D_;
#pragma unroll
            for (int u = 0; u < 4; u++) {
                const int c = lc0 + u * 4;
                float4 a = *(const float4*)(kp + c);
                Ks[lr * 65 + c + 0] = a.x; Ks[lr * 65 + c + 1] = a.y;
                Ks[lr * 65 + c + 2] = a.z; Ks[lr * 65 + c + 3] = a.w;
            }
            if (MODE == 1) {
                const float* vp = g_v + base + (size_t)(s0 + lr) * D_;
#pragma unroll
                for (int u = 0; u < 4; u++) {
                    const int c = lc0 + u * 4;
                    float4 a = *(const float4*)(vp + c);
                    Vs[lr * 65 + c + 0] = a.x; Vs[lr * 65 + c + 1] = a.y;
                    Vs[lr * 65 + c + 2] = a.z; Vs[lr * 65 + c + 3] = a.w;
                }
            }
        }
        __syncthreads();

        // phase 1: S = Qeff * K^T  (mask s>t; only bites on diagonal block)
        float sc[4][4] = {};
#pragma unroll 16
        for (int d = 0; d < 64; d++) {
            float av[4], bv[4];
#pragma unroll
            for (int i = 0; i < 4; i++) av[i] = Qs[(ty * 4 + i) * 65 + d];
#pragma unroll
            for (int jj = 0; jj < 4; jj++) bv[jj] = Ks[(tx * 4 + jj) * 65 + d];
#pragma unroll
            for (int i = 0; i < 4; i++)
#pragma unroll
                for (int jj = 0; jj < 4; jj++) sc[i][jj] += av[i] * bv[jj];
        }
#pragma unroll
        for (int i = 0; i < 4; i++) {
            const int tt = t0 + ty * 4 + i;
#pragma unroll
            for (int jj = 0; jj < 4; jj++) {
                const int ss = s0 + tx * 4 + jj;
                Ss[(ty * 4 + i) * 65 + tx * 4 + jj] = (ss <= tt) ? sc[i][jj] : 0.f;
            }
        }
        __syncthreads();

        // phase 2: O += S * V
#pragma unroll 16
        for (int s = 0; s < 64; s++) {
            float av[4], bv[4];
#pragma unroll
            for (int i = 0; i < 4; i++) av[i] = Ss[(ty * 4 + i) * 65 + s];
#pragma unroll
            for (int jj = 0; jj < 4; jj++) bv[jj] = Vs[s * 65 + tx * 4 + jj];
#pragma unroll
            for (int i = 0; i < 4; i++)
#pragma unroll
                for (int jj = 0; jj < 4; jj++) acc[i][jj] += av[i] * bv[jj];
        }
    }

    float* Out = (MODE == 0) ? g_o2 : g_ctx;
#pragma unroll
    for (int i = 0; i < 4; i++)
#pragma unroll
        for (int jj = 0; jj < 4; jj++)
            Out[base + (size_t)(t0 + ty * 4 + i) * D_ + tx * 4 + jj] = acc[i][jj];
}

// ============================================================
// Kernel 4: per-(b,h) normalization over (t,d), scatter to (b,s,dm)
// ============================================================
__device__ __forceinline__ double warpReduceSumD(double v) {
#pragma unroll
    for (int o = 16; o > 0; o >>= 1) v += __shfl_down_sync(0xffffffffu, v, o);
    return v;
}

__global__ void __launch_bounds__(512) gn_kernel(const float* __restrict__ gn_w,
                                                 const float* __restrict__ gn_b) {
    const int bh = blockIdx.x;            // 0..31
    const int b_idx = bh / H_, h = bh % H_;
    const float* src = g_ctx + (size_t)bh * S_ * D_;
    const int N = S_ * D_;                // 131072

    double sum = 0.0, sq = 0.0;
    for (int i = threadIdx.x; i < N; i += 512) {
        const float v = src[i];
        sum += v;
        sq += (double)v * (double)v;
    }
    __shared__ double ssum[16], ssq[16];
    const int lane = threadIdx.x & 31, wid = threadIdx.x >> 5;
    sum = warpReduceSumD(sum);
    sq = warpReduceSumD(sq);
    if (lane == 0) { ssum[wid] = sum; ssq[wid] = sq; }
    __syncthreads();
    __shared__ float s_mean, s_rstd;
    if (threadIdx.x == 0) {
        double ts = 0.0, tq = 0.0;
        for (int i = 0; i < 16; i++) { ts += ssum[i]; tq += ssq[i]; }
        const double mean = ts / (double)N;
        const double var = tq / (double)N - mean * mean;
        s_mean = (float)mean;
        s_rstd = (float)rsqrt(var + 1e-5);
    }
    __syncthreads();
    const float mean = s_mean, rstd = s_rstd;
    for (int i = threadIdx.x; i < N; i += 512) {
        const int t = i >> 6, d = i & 63;
        const int col = h * D_ + d;
        g_normed[((size_t)b_idx * S_ + t) * DM_ + col] =
            (src[i] - mean) * rstd * gn_w[col] + gn_b[col];
    }
}

// ============================================================
// Kernel 5: output projection.  out[m,n] = sum_k normed[m,k]*Wout[n,k] + b[n]
// M = 4096, N = 1024, K = 1024.
// ============================================================
__global__ void __launch_bounds__(256) out_gemm_kernel(
    const float* __restrict__ Wout, const float* __restrict__ bias,
    float* __restrict__ out) {
    __shared__ float As[16][68];
    __shared__ float Bs[16][68];
    const int bm = blockIdx.y * 64;
    const int bn = blockIdx.x * 64;
    const int tid = threadIdx.x;
    const int tx = tid & 15, ty = tid >> 4;
    const int lr = tid >> 2;
    const int lc = (tid & 3) * 4;

    float acc[4][4] = {};
    for (int k0 = 0; k0 < 1024; k0 += 16) {
        float4 a = *(const float4*)&g_normed[(size_t)(bm + lr) * 1024 + k0 + lc];
        float4 b = *(const float4*)&Wout[(size_t)(bn + lr) * 1024 + k0 + lc];
        As[lc + 0][lr] = a.x; As[lc + 1][lr] = a.y;
        As[lc + 2][lr] = a.z; As[lc + 3][lr] = a.w;
        Bs[lc + 0][lr] = b.x; Bs[lc + 1][lr] = b.y;
        Bs[lc + 2][lr] = b.z; Bs[lc + 3][lr] = b.w;
        __syncthreads();
#pragma unroll
        for (int kk = 0; kk < 16; kk++) {
            float av[4], bv[4];
#pragma unroll
            for (int i = 0; i < 4; i++) av[i] = As[kk][ty * 4 + i];
#pragma unroll
            for (int j = 0; j < 4; j++) bv[j] = Bs[kk][tx * 4 + j];
#pragma unroll
            for (int i = 0; i < 4; i++)
#pragma unroll
                for (int j = 0; j < 4; j++) acc[i][j] += av[i] * bv[j];
        }
        __syncthreads();
    }
#pragma unroll
    for (int i = 0; i < 4; i++) {
        const int m = bm + ty * 4 + i;
#pragma unroll
        for (int j = 0; j < 4; j++) {
            const int n = bn + tx * 4 + j;
            out[(size_t)m * DM_ + n] = acc[i][j] + bias[n];
        }
    }
}

// ============================================================
extern "C" void kernel_launch(void* const* d_in, const int* in_sizes, int n_in,
                              void* d_out, int out_size) {
    const float* x       = (const float*)d_in[0];
    const float* Wproj_w = (const float*)d_in[1];
    const float* Wproj_b = (const float*)d_in[2];
    const float* out_w   = (const float*)d_in[3];
    const float* out_b   = (const float*)d_in[4];
    const float* gn_w    = (const float*)d_in[5];
    const float* gn_b    = (const float*)d_in[6];
    float* out = (float*)d_out;

    // opt-in >48KB dynamic smem (idempotent, not a stream op)
    cudaFuncSetAttribute(attn_kernel<0>, cudaFuncAttributeMaxDynamicSharedMemorySize, 66560);
    cudaFuncSetAttribute(attn_kernel<1>, cudaFuncAttributeMaxDynamicSharedMemorySize, 66560);

    // 1) QKV projection + scatter
    qkv_gemm_kernel<<<dim3(48, 64), 256>>>(x, Wproj_w, Wproj_b);
    // 2) pass A: o2 = causal(q,k,k)
    attn_kernel<0><<<dim3(S_ / 64, BH_), 256, 3 * 64 * 65 * 4>>>();
    // 3) pass B: ctx = causal(2q-o2, k, v)
    attn_kernel<1><<<dim3(S_ / 64, BH_), 256, 4 * 64 * 65 * 4>>>();
    // 4) per-(b,h) norm + scatter
    gn_kernel<<<BH_, 512>>>(gn_w, gn_b);
    // 5) output projection
    out_gemm_kernel<<<dim3(DM_ / 64, (B_ * S_) / 64), 256>>>(out_w, out_b, out);
}